// round 4
// baseline (speedup 1.0000x reference)
#include <cuda_runtime.h>
#include <cstddef>

// Problem constants (fixed by the reference):
//   B_PAIRS=2048 pairs, each pair = 44 ligand nodes + 300 protein nodes (stride 344)
//   Only the ligand segment sums (even segments) feed the MLP.
//   MLP: 128 ->256 relu -> 128 relu -> 64 relu -> 1
#define B_PAIRS 2048
#define LIG     44
#define STRIDE  344
#define F_IN    128
#define N0      256
#define N1      128
#define N2      64
#define RTILE   4          // pairs per block -> grid 512
#define THREADS 256

typedef unsigned long long u64;

// ---------------- packed fp32x2 helpers (sm_103a FFMA2) --------------------
#define PACK_F32X2(d, lo, hi) \
    asm("mov.b64 %0, {%1, %2};" : "=l"(d) : "f"(lo), "f"(hi))
#define UNPACK_F32X2(lo, hi, v) \
    asm("mov.b64 {%0, %1}, %2;" : "=f"(lo), "=f"(hi) : "l"(v))
#define FMA_F32X2(d, a, b, c) \
    asm("fma.rn.f32x2 %0, %1, %2, %3;" : "=l"(d) : "l"(a), "l"(b), "l"(c))
#define ADD_F32X2(d, a, b) \
    asm("add.rn.f32x2 %0, %1, %2;" : "=l"(d) : "l"(a), "l"(b))

// ============================================================================
// One fused kernel: segment-sum (DRAM phase) + 4-layer MLP (issue phase).
// Activations live in SMEM *duplicated* ((x,x) u64) so inner loops need no
// packing: weights vector-load directly as packed column pairs.
// ============================================================================
__global__ void __launch_bounds__(THREADS)
fused_fcnn(const float* __restrict__ features,
           const float* __restrict__ W0, const float* __restrict__ b0,
           const float* __restrict__ W1, const float* __restrict__ b1,
           const float* __restrict__ W2, const float* __restrict__ b2,
           const float* __restrict__ Wout, const float* __restrict__ bout,
           float* __restrict__ out)
{
    __shared__ __align__(16) u64  xsD[F_IN][RTILE];   // 4 KB dup activations
    __shared__ __align__(16) u64  h0D[N0][RTILE];     // 8 KB
    __shared__ __align__(16) u64  h1D[N1][RTILE];     // 4 KB
    __shared__ __align__(16) float h2T[N2][RTILE];    // 1 KB
    __shared__ __align__(16) char pbuf[14336];        // partials / segsum scratch

    const int tid = threadIdx.x;
    const int p0  = blockIdx.x * RTILE;

    // ---------------- Phase S: ligand segment sum --------------------------
    // thread -> (pair pp = tid&3, float4 col c4 = (tid>>2)&31, half g = tid>>7)
    // 22 independent LDG.128 per thread; streaming.
    {
        const int pp = tid & 3;
        const int c4 = (tid >> 2) & 31;
        const int g  = tid >> 7;                     // 0/1
        const float4* src = reinterpret_cast<const float4*>(features)
                          + (size_t)(p0 + pp) * STRIDE * (F_IN / 4) + c4;
        float4 acc = make_float4(0.f, 0.f, 0.f, 0.f);
#pragma unroll
        for (int r = g; r < LIG; r += 2) {
            float4 v = __ldcs(src + (size_t)r * (F_IN / 4));
            acc.x += v.x; acc.y += v.y; acc.z += v.z; acc.w += v.w;
        }
        float4* part = reinterpret_cast<float4*>(pbuf);   // [4][32]
        if (g == 1) part[pp * 32 + c4] = acc;
        __syncthreads();
        if (g == 0) {
            float4 v = part[pp * 32 + c4];
            acc.x += v.x; acc.y += v.y; acc.z += v.z; acc.w += v.w;
            u64 d0, d1, d2, d3;
            PACK_F32X2(d0, acc.x, acc.x);
            PACK_F32X2(d1, acc.y, acc.y);
            PACK_F32X2(d2, acc.z, acc.z);
            PACK_F32X2(d3, acc.w, acc.w);
            xsD[c4 * 4 + 0][pp] = d0;
            xsD[c4 * 4 + 1][pp] = d1;
            xsD[c4 * 4 + 2][pp] = d2;
            xsD[c4 * 4 + 3][pp] = d3;
        }
    }
    __syncthreads();

    // ---------------- Layer 0: [4,128]@[128,256]+b relu, k-split x4 --------
    // thread = (cg = tid&63 -> cols 4cg..4cg+3, kq = tid>>6 -> k quarter)
    {
        const int cg = tid & 63;
        const int kq = tid >> 6;
        u64 acc[8];                                   // [row][colpair]
        if (kq == 0) {
            ulonglong2 b4 = *reinterpret_cast<const ulonglong2*>(b0 + 4 * cg);
#pragma unroll
            for (int r = 0; r < 4; ++r) { acc[r*2] = b4.x; acc[r*2+1] = b4.y; }
        } else {
#pragma unroll
            for (int i = 0; i < 8; ++i) acc[i] = 0ull;
        }
        const float* Wp = W0 + (size_t)kq * 32 * N0 + 4 * cg;
#pragma unroll 8
        for (int kk = 0; kk < 32; ++kk) {
            ulonglong2 w = *reinterpret_cast<const ulonglong2*>(Wp + kk * N0);
#pragma unroll
            for (int r = 0; r < 4; ++r) {
                u64 a = xsD[kq * 32 + kk][r];        // broadcast LDS.64
                FMA_F32X2(acc[r*2],   a, w.x, acc[r*2]);
                FMA_F32X2(acc[r*2+1], a, w.y, acc[r*2+1]);
            }
        }
        u64* pL0 = reinterpret_cast<u64*>(pbuf);      // [3][64][8] = 12 KB
        if (kq > 0) {
#pragma unroll
            for (int i = 0; i < 8; ++i) pL0[((kq-1) * 64 + cg) * 8 + i] = acc[i];
        }
        __syncthreads();
        if (kq == 0) {
#pragma unroll
            for (int t = 0; t < 3; ++t)
#pragma unroll
                for (int i = 0; i < 8; ++i) {
                    u64 q = pL0[(t * 64 + cg) * 8 + i];
                    ADD_F32X2(acc[i], acc[i], q);
                }
#pragma unroll
            for (int r = 0; r < 4; ++r)
#pragma unroll
                for (int cp = 0; cp < 2; ++cp) {
                    float v0, v1; UNPACK_F32X2(v0, v1, acc[r*2+cp]);
                    v0 = fmaxf(v0, 0.f); v1 = fmaxf(v1, 0.f);
                    u64 d0, d1; PACK_F32X2(d0, v0, v0); PACK_F32X2(d1, v1, v1);
                    h0D[4*cg + 2*cp    ][r] = d0;
                    h0D[4*cg + 2*cp + 1][r] = d1;
                }
        }
    }
    __syncthreads();

    // ---------------- Layer 1: [4,256]@[256,128]+b relu, k-split x8 --------
    // thread = (cg = tid&31 -> cols 4cg..4cg+3, kq = tid>>5 -> k eighth of 32)
    {
        const int cg = tid & 31;
        const int kq = tid >> 5;
        u64 acc[8];
        if (kq == 0) {
            ulonglong2 b4 = *reinterpret_cast<const ulonglong2*>(b1 + 4 * cg);
#pragma unroll
            for (int r = 0; r < 4; ++r) { acc[r*2] = b4.x; acc[r*2+1] = b4.y; }
        } else {
#pragma unroll
            for (int i = 0; i < 8; ++i) acc[i] = 0ull;
        }
        const float* Wp = W1 + (size_t)kq * 32 * N1 + 4 * cg;
#pragma unroll 8
        for (int kk = 0; kk < 32; ++kk) {
            ulonglong2 w = *reinterpret_cast<const ulonglong2*>(Wp + kk * N1);
#pragma unroll
            for (int r = 0; r < 4; ++r) {
                u64 a = h0D[kq * 32 + kk][r];
                FMA_F32X2(acc[r*2],   a, w.x, acc[r*2]);
                FMA_F32X2(acc[r*2+1], a, w.y, acc[r*2+1]);
            }
        }
        u64* pL1 = reinterpret_cast<u64*>(pbuf);      // [7][32][8] = 14 KB
        if (kq > 0) {
#pragma unroll
            for (int i = 0; i < 8; ++i) pL1[((kq-1) * 32 + cg) * 8 + i] = acc[i];
        }
        __syncthreads();
        if (kq == 0) {
#pragma unroll
            for (int t = 0; t < 7; ++t)
#pragma unroll
                for (int i = 0; i < 8; ++i) {
                    u64 q = pL1[(t * 32 + cg) * 8 + i];
                    ADD_F32X2(acc[i], acc[i], q);
                }
#pragma unroll
            for (int r = 0; r < 4; ++r)
#pragma unroll
                for (int cp = 0; cp < 2; ++cp) {
                    float v0, v1; UNPACK_F32X2(v0, v1, acc[r*2+cp]);
                    v0 = fmaxf(v0, 0.f); v1 = fmaxf(v1, 0.f);
                    u64 d0, d1; PACK_F32X2(d0, v0, v0); PACK_F32X2(d1, v1, v1);
                    h1D[4*cg + 2*cp    ][r] = d0;
                    h1D[4*cg + 2*cp + 1][r] = d1;
                }
        }
    }
    __syncthreads();

    // ---------------- Layer 2: [4,128]@[128,64]+b relu, k-split x8 ---------
    // thread = (cg = tid&31 -> cols 2cg,2cg+1, kq = tid>>5 -> k eighth of 16)
    {
        const int cg = tid & 31;
        const int kq = tid >> 5;
        u64 acc[4];                                   // [row], one colpair
        if (kq == 0) {
            u64 b2p = *reinterpret_cast<const u64*>(b2 + 2 * cg);
#pragma unroll
            for (int r = 0; r < 4; ++r) acc[r] = b2p;
        } else {
#pragma unroll
            for (int r = 0; r < 4; ++r) acc[r] = 0ull;
        }
        const float* Wp = W2 + (size_t)kq * 16 * N2 + 2 * cg;
#pragma unroll
        for (int kk = 0; kk < 16; ++kk) {
            u64 w = *reinterpret_cast<const u64*>(Wp + kk * N2);
#pragma unroll
            for (int r = 0; r < 4; ++r) {
                u64 a = h1D[kq * 16 + kk][r];
                FMA_F32X2(acc[r], a, w, acc[r]);
            }
        }
        u64* pL2 = reinterpret_cast<u64*>(pbuf);      // [7][32][4] = 7 KB
        if (kq > 0) {
#pragma unroll
            for (int r = 0; r < 4; ++r) pL2[((kq-1) * 32 + cg) * 4 + r] = acc[r];
        }
        __syncthreads();
        if (kq == 0) {
#pragma unroll
            for (int t = 0; t < 7; ++t)
#pragma unroll
                for (int r = 0; r < 4; ++r) {
                    u64 q = pL2[(t * 32 + cg) * 4 + r];
                    ADD_F32X2(acc[r], acc[r], q);
                }
#pragma unroll
            for (int r = 0; r < 4; ++r) {
                float v0, v1; UNPACK_F32X2(v0, v1, acc[r]);
                h2T[2*cg    ][r] = fmaxf(v0, 0.f);
                h2T[2*cg + 1][r] = fmaxf(v1, 0.f);
            }
        }
    }
    __syncthreads();

    // ---------------- Output: [4,64]@[64,1]+b -------------------------------
    {
        const int warp = tid >> 5;
        const int lane = tid & 31;
        if (warp < RTILE) {
            float s = h2T[2 * lane][warp]     * Wout[2 * lane]
                    + h2T[2 * lane + 1][warp] * Wout[2 * lane + 1];
#pragma unroll
            for (int o = 16; o > 0; o >>= 1)
                s += __shfl_down_sync(0xffffffffu, s, o);
            if (lane == 0)
                out[p0 + warp] = s + bout[0];
        }
    }
}

// d_in order (metadata): [0] batch_num_nodes (unused), [1] features,
// [2] W0, [3] b0, [4] W1, [5] b1, [6] W2, [7] b2, [8] Wout, [9] bout.
extern "C" void kernel_launch(void* const* d_in, const int* in_sizes, int n_in,
                              void* d_out, int out_size)
{
    const float* features = (const float*)d_in[1];
    const float* W0   = (const float*)d_in[2];
    const float* b0   = (const float*)d_in[3];
    const float* W1   = (const float*)d_in[4];
    const float* b1   = (const float*)d_in[5];
    const float* W2   = (const float*)d_in[6];
    const float* b2   = (const float*)d_in[7];
    const float* Wout = (const float*)d_in[8];
    const float* bout = (const float*)d_in[9];
    float* out = (float*)d_out;

    fused_fcnn<<<B_PAIRS / RTILE, THREADS>>>(features, W0, b0, W1, b1,
                                             W2, b2, Wout, bout, out);
}

// round 5
// speedup vs baseline: 1.0721x; 1.0721x over previous
#include <cuda_runtime.h>
#include <cstddef>

// Problem constants (fixed by the reference):
//   B_PAIRS=2048 pairs, each pair = 44 ligand nodes + 300 protein nodes (stride 344)
//   Only the ligand segment sums (even segments) feed the MLP.
//   MLP: 128 ->256 relu -> 128 relu -> 64 relu -> 1
#define B_PAIRS 2048
#define LIG     44
#define STRIDE  344
#define F_IN    128
#define N0      256
#define N1      128
#define N2      64
#define RTILE   2          // pairs per MLP block -> grid 1024
#define THREADS 256

typedef unsigned long long u64;

// 1 MB scratch for the per-pair feature sums.
__device__ float g_xs[B_PAIRS * F_IN];

// ---------------- packed fp32x2 helpers (sm_103a FFMA2) --------------------
#define PACK_F32X2(d, lo, hi) \
    asm("mov.b64 %0, {%1, %2};" : "=l"(d) : "f"(lo), "f"(hi))
#define UNPACK_F32X2(lo, hi, v) \
    asm("mov.b64 {%0, %1}, %2;" : "=f"(lo), "=f"(hi) : "l"(v))
#define FMA_F32X2(d, a, b, c) \
    asm("fma.rn.f32x2 %0, %1, %2, %3;" : "=l"(d) : "l"(a), "l"(b), "l"(c))
#define ADD_F32X2(d, a, b) \
    asm("add.rn.f32x2 %0, %1, %2;" : "=l"(d) : "l"(a), "l"(b))

// ============================================================================
// Kernel A: ligand segment sum. One block per pair; DRAM-bound (46 MB once).
// ============================================================================
__global__ void __launch_bounds__(THREADS)
seg_sum_kernel(const float* __restrict__ features)
{
    __shared__ float4 part[8][32];
    const int tid  = threadIdx.x;
    const int pair = blockIdx.x;
    const int c4   = tid & 31;
    const int g    = tid >> 5;

    const float4* src = reinterpret_cast<const float4*>(features)
                      + (size_t)pair * STRIDE * (F_IN / 4) + c4;
    float4 acc = make_float4(0.f, 0.f, 0.f, 0.f);
#pragma unroll
    for (int r = g; r < LIG; r += 8) {
        float4 v = __ldcs(src + (size_t)r * (F_IN / 4));
        acc.x += v.x; acc.y += v.y; acc.z += v.z; acc.w += v.w;
    }
    part[g][c4] = acc;
    __syncthreads();

    if (tid < 32) {
        float4 s = part[0][tid];
#pragma unroll
        for (int gg = 1; gg < 8; ++gg) {
            float4 v = part[gg][tid];
            s.x += v.x; s.y += v.y; s.z += v.z; s.w += v.w;
        }
        reinterpret_cast<float4*>(g_xs)[pair * (F_IN / 4) + tid] = s;
    }
}

// ============================================================================
// Kernel B: 4-layer MLP on 2 rows per block (grid=1024), dup-activation
// layout: SMEM holds (x,x) u64 per (feature,row); one LDS.128 = both rows,
// one LDG.128 = 2 packed weight column-pairs. Inner loop has zero packs.
// ============================================================================
__global__ void __launch_bounds__(THREADS)
mlp_kernel(const float* __restrict__ W0, const float* __restrict__ b0,
           const float* __restrict__ W1, const float* __restrict__ b1,
           const float* __restrict__ W2, const float* __restrict__ b2,
           const float* __restrict__ Wout, const float* __restrict__ bout,
           float* __restrict__ out)
{
    __shared__ __align__(16) u64  xsD[F_IN][RTILE];   // 2 KB
    __shared__ __align__(16) u64  h0D[N0][RTILE];     // 4 KB
    __shared__ __align__(16) u64  h1D[N1][RTILE];     // 2 KB
    __shared__ __align__(16) float h2T[N2][RTILE];    // 0.5 KB
    __shared__ __align__(16) u64  pbuf[7 * 32 * 4];   // 7 KB partials

    const int tid = threadIdx.x;
    const int p0  = blockIdx.x * RTILE;

    // Load 2 summed rows, duplicate-pack into SMEM.
    if (tid < 64) {
        const int pp = tid & 1;
        const int c4 = tid >> 1;                 // 0..31
        float4 v = reinterpret_cast<const float4*>(g_xs)
                       [(size_t)(p0 + pp) * (F_IN / 4) + c4];
        u64 d0, d1, d2, d3;
        PACK_F32X2(d0, v.x, v.x); PACK_F32X2(d1, v.y, v.y);
        PACK_F32X2(d2, v.z, v.z); PACK_F32X2(d3, v.w, v.w);
        xsD[c4 * 4 + 0][pp] = d0;
        xsD[c4 * 4 + 1][pp] = d1;
        xsD[c4 * 4 + 2][pp] = d2;
        xsD[c4 * 4 + 3][pp] = d3;
    }
    __syncthreads();

    // ---------------- Layer 0: [2,128]@[128,256]+b relu, k-split x4 --------
    // thread = (cg = tid&63 -> cols 4cg..4cg+3, kq = tid>>6)
    {
        const int cg = tid & 63;
        const int kq = tid >> 6;
        u64 acc0, acc1, acc2, acc3;              // [row0:p0,p1, row1:p0,p1]
        if (kq == 0) {
            ulonglong2 bp = *reinterpret_cast<const ulonglong2*>(b0 + 4 * cg);
            acc0 = bp.x; acc1 = bp.y; acc2 = bp.x; acc3 = bp.y;
        } else { acc0 = acc1 = acc2 = acc3 = 0ull; }
        const float* Wp = W0 + (size_t)kq * 32 * N0 + 4 * cg;
#pragma unroll 8
        for (int kk = 0; kk < 32; ++kk) {
            ulonglong2 w = *reinterpret_cast<const ulonglong2*>(Wp + kk * N0);
            ulonglong2 a = *reinterpret_cast<const ulonglong2*>(
                               &xsD[kq * 32 + kk][0]);
            FMA_F32X2(acc0, a.x, w.x, acc0);
            FMA_F32X2(acc1, a.x, w.y, acc1);
            FMA_F32X2(acc2, a.y, w.x, acc2);
            FMA_F32X2(acc3, a.y, w.y, acc3);
        }
        if (kq > 0) {
            ulonglong2* dst = reinterpret_cast<ulonglong2*>(
                                  &pbuf[((kq - 1) * 64 + cg) * 4]);
            dst[0] = make_ulonglong2(acc0, acc1);
            dst[1] = make_ulonglong2(acc2, acc3);
        }
        __syncthreads();
        if (kq == 0) {
#pragma unroll
            for (int t = 0; t < 3; ++t) {
                const ulonglong2* q = reinterpret_cast<const ulonglong2*>(
                                          &pbuf[(t * 64 + cg) * 4]);
                ulonglong2 q0 = q[0], q1 = q[1];
                ADD_F32X2(acc0, acc0, q0.x); ADD_F32X2(acc1, acc1, q0.y);
                ADD_F32X2(acc2, acc2, q1.x); ADD_F32X2(acc3, acc3, q1.y);
            }
            float r0c0, r0c1, r0c2, r0c3, r1c0, r1c1, r1c2, r1c3;
            UNPACK_F32X2(r0c0, r0c1, acc0); UNPACK_F32X2(r0c2, r0c3, acc1);
            UNPACK_F32X2(r1c0, r1c1, acc2); UNPACK_F32X2(r1c2, r1c3, acc3);
            u64 d;
            ulonglong2 st;
            PACK_F32X2(d, fmaxf(r0c0,0.f), fmaxf(r0c0,0.f)); st.x = d;
            PACK_F32X2(d, fmaxf(r1c0,0.f), fmaxf(r1c0,0.f)); st.y = d;
            *reinterpret_cast<ulonglong2*>(&h0D[4*cg + 0][0]) = st;
            PACK_F32X2(d, fmaxf(r0c1,0.f), fmaxf(r0c1,0.f)); st.x = d;
            PACK_F32X2(d, fmaxf(r1c1,0.f), fmaxf(r1c1,0.f)); st.y = d;
            *reinterpret_cast<ulonglong2*>(&h0D[4*cg + 1][0]) = st;
            PACK_F32X2(d, fmaxf(r0c2,0.f), fmaxf(r0c2,0.f)); st.x = d;
            PACK_F32X2(d, fmaxf(r1c2,0.f), fmaxf(r1c2,0.f)); st.y = d;
            *reinterpret_cast<ulonglong2*>(&h0D[4*cg + 2][0]) = st;
            PACK_F32X2(d, fmaxf(r0c3,0.f), fmaxf(r0c3,0.f)); st.x = d;
            PACK_F32X2(d, fmaxf(r1c3,0.f), fmaxf(r1c3,0.f)); st.y = d;
            *reinterpret_cast<ulonglong2*>(&h0D[4*cg + 3][0]) = st;
        }
    }
    __syncthreads();

    // ---------------- Layer 1: [2,256]@[256,128]+b relu, k-split x8 --------
    // thread = (cg = tid&31 -> cols 4cg..4cg+3, kq = tid>>5)
    {
        const int cg = tid & 31;
        const int kq = tid >> 5;
        u64 acc0, acc1, acc2, acc3;
        if (kq == 0) {
            ulonglong2 bp = *reinterpret_cast<const ulonglong2*>(b1 + 4 * cg);
            acc0 = bp.x; acc1 = bp.y; acc2 = bp.x; acc3 = bp.y;
        } else { acc0 = acc1 = acc2 = acc3 = 0ull; }
        const float* Wp = W1 + (size_t)kq * 32 * N1 + 4 * cg;
#pragma unroll 8
        for (int kk = 0; kk < 32; ++kk) {
            ulonglong2 w = *reinterpret_cast<const ulonglong2*>(Wp + kk * N1);
            ulonglong2 a = *reinterpret_cast<const ulonglong2*>(
                               &h0D[kq * 32 + kk][0]);
            FMA_F32X2(acc0, a.x, w.x, acc0);
            FMA_F32X2(acc1, a.x, w.y, acc1);
            FMA_F32X2(acc2, a.y, w.x, acc2);
            FMA_F32X2(acc3, a.y, w.y, acc3);
        }
        if (kq > 0) {
            ulonglong2* dst = reinterpret_cast<ulonglong2*>(
                                  &pbuf[((kq - 1) * 32 + cg) * 4]);
            dst[0] = make_ulonglong2(acc0, acc1);
            dst[1] = make_ulonglong2(acc2, acc3);
        }
        __syncthreads();
        if (kq == 0) {
#pragma unroll
            for (int t = 0; t < 7; ++t) {
                const ulonglong2* q = reinterpret_cast<const ulonglong2*>(
                                          &pbuf[(t * 32 + cg) * 4]);
                ulonglong2 q0 = q[0], q1 = q[1];
                ADD_F32X2(acc0, acc0, q0.x); ADD_F32X2(acc1, acc1, q0.y);
                ADD_F32X2(acc2, acc2, q1.x); ADD_F32X2(acc3, acc3, q1.y);
            }
            float r0c0, r0c1, r0c2, r0c3, r1c0, r1c1, r1c2, r1c3;
            UNPACK_F32X2(r0c0, r0c1, acc0); UNPACK_F32X2(r0c2, r0c3, acc1);
            UNPACK_F32X2(r1c0, r1c1, acc2); UNPACK_F32X2(r1c2, r1c3, acc3);
            u64 d;
            ulonglong2 st;
            PACK_F32X2(d, fmaxf(r0c0,0.f), fmaxf(r0c0,0.f)); st.x = d;
            PACK_F32X2(d, fmaxf(r1c0,0.f), fmaxf(r1c0,0.f)); st.y = d;
            *reinterpret_cast<ulonglong2*>(&h1D[4*cg + 0][0]) = st;
            PACK_F32X2(d, fmaxf(r0c1,0.f), fmaxf(r0c1,0.f)); st.x = d;
            PACK_F32X2(d, fmaxf(r1c1,0.f), fmaxf(r1c1,0.f)); st.y = d;
            *reinterpret_cast<ulonglong2*>(&h1D[4*cg + 1][0]) = st;
            PACK_F32X2(d, fmaxf(r0c2,0.f), fmaxf(r0c2,0.f)); st.x = d;
            PACK_F32X2(d, fmaxf(r1c2,0.f), fmaxf(r1c2,0.f)); st.y = d;
            *reinterpret_cast<ulonglong2*>(&h1D[4*cg + 2][0]) = st;
            PACK_F32X2(d, fmaxf(r0c3,0.f), fmaxf(r0c3,0.f)); st.x = d;
            PACK_F32X2(d, fmaxf(r1c3,0.f), fmaxf(r1c3,0.f)); st.y = d;
            *reinterpret_cast<ulonglong2*>(&h1D[4*cg + 3][0]) = st;
        }
    }
    __syncthreads();

    // ---------------- Layer 2: [2,128]@[128,64]+b relu, k-split x8 ---------
    // thread = (cg = tid&31 -> cols 2cg,2cg+1, kq = tid>>5)
    {
        const int cg = tid & 31;
        const int kq = tid >> 5;
        u64 acc0, acc1;                          // row0 pair, row1 pair
        if (kq == 0) {
            u64 bp = *reinterpret_cast<const u64*>(b2 + 2 * cg);
            acc0 = bp; acc1 = bp;
        } else { acc0 = acc1 = 0ull; }
        const float* Wp = W2 + (size_t)kq * 16 * N2 + 2 * cg;
#pragma unroll
        for (int kk = 0; kk < 16; ++kk) {
            u64 w = *reinterpret_cast<const u64*>(Wp + kk * N2);
            ulonglong2 a = *reinterpret_cast<const ulonglong2*>(
                               &h1D[kq * 16 + kk][0]);
            FMA_F32X2(acc0, a.x, w, acc0);
            FMA_F32X2(acc1, a.y, w, acc1);
        }
        if (kq > 0) {
            ulonglong2* dst = reinterpret_cast<ulonglong2*>(
                                  &pbuf[((kq - 1) * 32 + cg) * 2]);
            dst[0] = make_ulonglong2(acc0, acc1);
        }
        __syncthreads();
        if (kq == 0) {
#pragma unroll
            for (int t = 0; t < 7; ++t) {
                ulonglong2 q = *reinterpret_cast<const ulonglong2*>(
                                   &pbuf[(t * 32 + cg) * 2]);
                ADD_F32X2(acc0, acc0, q.x);
                ADD_F32X2(acc1, acc1, q.y);
            }
            float v0, v1;
            UNPACK_F32X2(v0, v1, acc0);
            h2T[2*cg    ][0] = fmaxf(v0, 0.f);
            h2T[2*cg + 1][0] = fmaxf(v1, 0.f);
            UNPACK_F32X2(v0, v1, acc1);
            h2T[2*cg    ][1] = fmaxf(v0, 0.f);
            h2T[2*cg + 1][1] = fmaxf(v1, 0.f);
        }
    }
    __syncthreads();

    // ---------------- Output: [2,64]@[64,1]+b -------------------------------
    {
        const int warp = tid >> 5;
        const int lane = tid & 31;
        if (warp < RTILE) {
            float s = h2T[2 * lane][warp]     * Wout[2 * lane]
                    + h2T[2 * lane + 1][warp] * Wout[2 * lane + 1];
#pragma unroll
            for (int o = 16; o > 0; o >>= 1)
                s += __shfl_down_sync(0xffffffffu, s, o);
            if (lane == 0)
                out[p0 + warp] = s + bout[0];
        }
    }
}

// d_in order (metadata): [0] batch_num_nodes (unused), [1] features,
// [2] W0, [3] b0, [4] W1, [5] b1, [6] W2, [7] b2, [8] Wout, [9] bout.
extern "C" void kernel_launch(void* const* d_in, const int* in_sizes, int n_in,
                              void* d_out, int out_size)
{
    const float* features = (const float*)d_in[1];
    const float* W0   = (const float*)d_in[2];
    const float* b0   = (const float*)d_in[3];
    const float* W1   = (const float*)d_in[4];
    const float* b1   = (const float*)d_in[5];
    const float* W2   = (const float*)d_in[6];
    const float* b2   = (const float*)d_in[7];
    const float* Wout = (const float*)d_in[8];
    const float* bout = (const float*)d_in[9];
    float* out = (float*)d_out;

    seg_sum_kernel<<<B_PAIRS, THREADS>>>(features);
    mlp_kernel<<<B_PAIRS / RTILE, THREADS>>>(W0, b0, W1, b1, W2, b2,
                                             Wout, bout, out);
}